// round 17
// baseline (speedup 1.0000x reference)
#include <cuda_runtime.h>
#include <cuda_bf16.h>
#include <math.h>

#define F 128
#define NMAX 50000
#define EMAX 800000
#define CAP 64      // bucket capacity per destination row (P(deg>=64) ~ 1e-13)

typedef unsigned int       u32;
typedef unsigned short     u16;
typedef unsigned long long u64;

// static scratch (no allocations allowed; zero-initialized at load)
__device__ u16    g_Shi[(size_t)NMAX * F];         // bf16 hi of S
__device__ u16    g_Slo[(size_t)NMAX * F];         // bf16 residual of S
__device__ float2 g_slots[(size_t)NMAX * CAP];     // (src_bits, w) buckets
__device__ int    g_cnt[NMAX];                     // reset by epilogue for next call
__device__ float4 g_over[EMAX];                    // overflow edges
__device__ int    g_overcnt;

// ---------------------------------------------------------------------------
// Kernel 1: bucket fill. One thread per edge (proven throughput-bound config).
// ---------------------------------------------------------------------------
__global__ void fill_kernel(const float* __restrict__ edge_w,
                            const int* __restrict__ edge_src,
                            const int* __restrict__ edge_dst,
                            int E) {
    int e = blockIdx.x * blockDim.x + threadIdx.x;
    if (e >= E) return;
    int d = edge_dst[e];
    int s = edge_src[e];
    float w = edge_w[e];
    int pos = atomicAdd(&g_cnt[d], 1);
    if (pos < CAP) {
        g_slots[(size_t)d * CAP + pos] = make_float2(__int_as_float(s), w);
    } else {
        int o = atomicAdd(&g_overcnt, 1);
        if (o < EMAX)
            g_over[o] = make_float4(__int_as_float(s), __int_as_float(d), w, 0.f);
    }
}

// ---------------------------------------------------------------------------
// Kernel 2: gather + S fuse + bf16 hi/lo split. One warp per row (R12-proven).
// ---------------------------------------------------------------------------
__global__ void gather_kernel(const float* __restrict__ x,
                              const float* __restrict__ h0,
                              const float* __restrict__ alpha_p,
                              int Nn) {
    int gtid = blockIdx.x * blockDim.x + threadIdx.x;
    int row = gtid >> 5;
    int lane = gtid & 31;
    if (row >= Nn) return;

    float alpha = alpha_p[0];
    float oma = 1.0f - alpha;

    int cnt_raw = g_cnt[row];
    int cnt = min(cnt_raw, CAP);

    float4 acc = make_float4(0.f, 0.f, 0.f, 0.f);
    const float2* slotp = g_slots + (size_t)row * CAP;

    for (int base = 0; base < cnt; base += 32) {
        int m = min(32, cnt - base);
        float2 myslot = (lane < m) ? slotp[base + lane] : make_float2(0.f, 0.f);
        int ms = __float_as_int(myslot.x);
        #pragma unroll 4
        for (int e = 0; e < m; e++) {
            int   s  = __shfl_sync(0xffffffffu, ms, e);
            float wt = __shfl_sync(0xffffffffu, myslot.y, e);
            float4 v = ((const float4*)(x + (size_t)s * F))[lane];
            acc.x += wt * v.x;
            acc.y += wt * v.y;
            acc.z += wt * v.z;
            acc.w += wt * v.w;
        }
    }

    if (cnt_raw > CAP) {                       // statistically never
        int oc = g_overcnt;
        if (oc > EMAX) oc = EMAX;
        for (int o = 0; o < oc; o++) {
            float4 ov = g_over[o];
            if (__float_as_int(ov.y) == row) {
                int s = __float_as_int(ov.x);
                float wt = ov.z;
                float4 v = ((const float4*)(x + (size_t)s * F))[lane];
                acc.x += wt * v.x;
                acc.y += wt * v.y;
                acc.z += wt * v.z;
                acc.w += wt * v.w;
            }
        }
    }

    float4 hv = ((const float4*)(h0 + (size_t)row * F))[lane];
    float Sx = oma * acc.x + alpha * hv.x;
    float Sy = oma * acc.y + alpha * hv.y;
    float Sz = oma * acc.z + alpha * hv.z;
    float Sw = oma * acc.w + alpha * hv.w;

    __nv_bfloat162 h01 = __floats2bfloat162_rn(Sx, Sy);
    __nv_bfloat162 h23 = __floats2bfloat162_rn(Sz, Sw);
    __nv_bfloat162 l01 = __floats2bfloat162_rn(
        Sx - __bfloat162float(h01.x), Sy - __bfloat162float(h01.y));
    __nv_bfloat162 l23 = __floats2bfloat162_rn(
        Sz - __bfloat162float(h23.x), Sw - __bfloat162float(h23.y));
    u64 hvv = (u64)(*(u32*)&h01) | ((u64)(*(u32*)&h23) << 32);
    u64 lvv = (u64)(*(u32*)&l01) | ((u64)(*(u32*)&l23) << 32);
    *(u64*)&g_Shi[(size_t)row * F + 4 * lane] = hvv;
    *(u64*)&g_Slo[(size_t)row * F + 4 * lane] = lvv;
}

// ---------------------------------------------------------------------------
// Kernel 3: HMMA epilogue, double-buffered, 3 INDEPENDENT ACC CHAINS.
//   out = S @ W' + x;  D = Sa@Wa + Sb@Wa + Sa@Wb (fp32 accum).
// R17 vs R16: per n-tile the 3 terms accumulate into SEPARATE registers
// (acc_hh/acc_lh/acc_hl, summed at writeout) -> 6 independent MMA chains
// of depth 8 per warp (was 2 chains of depth 24) -> HMMA latency hidden.
// Register budget balanced by demoting Bl fragments to smem LDS (WTb is
// already resident; conflict-free pattern: bank = 4*(n%8)+cq).
// ---------------------------------------------------------------------------
#define SPAD 136                        // u16 row stride (272 bytes)
#define OFF_WTA 0
#define OFF_WTB (128 * SPAD * 2)        // 34816
#define OFF_S   (2 * 128 * SPAD * 2)    // 69632
#define BUFSZ   (16 * SPAD * 2)         // 4352 bytes per Sa/Sb buffer
#define SMEM_EPI (OFF_S + 4 * BUFSZ)    // 87040 bytes

#define MMA_BF16(c, a0, a1, a2, a3, b0, b1) \
    asm volatile("mma.sync.aligned.m16n8k16.row.col.f32.bf16.bf16.f32 " \
        "{%0,%1,%2,%3}, {%4,%5,%6,%7}, {%8,%9}, {%0,%1,%2,%3};" \
        : "+f"((c)[0]), "+f"((c)[1]), "+f"((c)[2]), "+f"((c)[3]) \
        : "r"(a0), "r"(a1), "r"(a2), "r"(a3), "r"(b0), "r"(b1))

#define LDMATRIX_X4(r0, r1, r2, r3, addr) \
    asm volatile("ldmatrix.sync.aligned.m8n8.x4.shared.b16 {%0,%1,%2,%3}, [%4];" \
        : "=r"(r0), "=r"(r1), "=r"(r2), "=r"(r3) : "r"(addr))

__device__ __forceinline__ u32 smem_u32(const void* p) {
    u32 a;
    asm("{ .reg .u64 t; cvta.to.shared.u64 t, %1; cvt.u32.u64 %0, t; }"
        : "=r"(a) : "l"(p));
    return a;
}

__global__ void __launch_bounds__(256, 2)
mma_epilogue_kernel(const float* __restrict__ x,
                    const float* __restrict__ weight,
                    const float* __restrict__ lamda_p,
                    const int* __restrict__ l_p,
                    float* __restrict__ out,
                    int Nn) {
    extern __shared__ char sm[];
    u16* WTa = (u16*)(sm + OFF_WTA);
    u16* WTb = (u16*)(sm + OFF_WTB);
    u16* Sa0 = (u16*)(sm + OFF_S);
    u16* Sb0 = (u16*)(sm + OFF_S + BUFSZ);
    u16* Sa1 = (u16*)(sm + OFF_S + 2 * BUFSZ);
    u16* Sb1 = (u16*)(sm + OFF_S + 3 * BUFSZ);

    int tid  = threadIdx.x;
    int lane = tid & 31;
    int wrp  = tid >> 5;

    // reset counters for the NEXT invocation (off the critical path)
    {
        int gid = blockIdx.x * blockDim.x + tid;
        if (gid < Nn) g_cnt[gid] = 0;
        if (gid == 0) g_overcnt = 0;
    }

    float theta = logf(lamda_p[0] / (float)l_p[0] + 1.0f);
    float omt = 1.0f - theta;

    // Build WT hi/lo: WT[n][k] = W'[k][n] = theta*W[k][n] + (k==n)*(1-theta)
    for (int i = tid; i < F * F; i += 256) {
        int k = i >> 7;
        int n = i & 127;
        float v = theta * weight[i];
        if (k == n) v += omt;
        __nv_bfloat16 h = __float2bfloat16(v);
        float res = v - __bfloat162float(h);
        __nv_bfloat16 l = __float2bfloat16(res);
        WTa[n * SPAD + k] = *(u16*)&h;
        WTb[n * SPAD + k] = *(u16*)&l;
    }
    __syncthreads();

    int m0 = lane >> 2;                // fragment row (0..7)
    int cq = lane & 3;                 // k/n quad (0..3)
    int nt0 = wrp * 2;                 // this warp's two n-tiles

    int n0 = (nt0 + 0) * 8 + m0;
    int n1 = (nt0 + 1) * 8 + m0;
    const u16* wb0 = WTb + n0 * SPAD;  // Bl rows stay in smem (LDS per ks)
    const u16* wb1 = WTb + n1 * SPAD;
    int kbase = cq * 2;

    // ---- hoist ONLY the Bh fragments into registers: 32 u32 regs
    u32 Bh[2][8][2];
    #pragma unroll
    for (int j = 0; j < 2; j++) {
        int n = (nt0 + j) * 8 + m0;
        #pragma unroll
        for (int ks = 0; ks < 8; ks++) {
            int kk = ks * 16 + kbase;
            Bh[j][ks][0] = *(u32*)&WTa[n * SPAD + kk];
            Bh[j][ks][1] = *(u32*)&WTa[n * SPAD + kk + 8];
        }
    }

    // ldmatrix lane addressing: row = lane&15, col-block = (lane>>4)*8
    u32 lmoff = ((lane & 15) * SPAD + ((lane >> 4) << 3)) * 2;
    u32 aSa0 = smem_u32(Sa0) + lmoff;
    u32 aSb0 = smem_u32(Sb0) + lmoff;
    u32 aSa1 = smem_u32(Sa1) + lmoff;
    u32 aSb1 = smem_u32(Sb1) + lmoff;

    // staging assignment: thread -> (row sr, 8-col segment seg)
    int sr  = tid >> 4;
    int seg = tid & 15;

    int ntiles = (Nn + 15) >> 4;

    // ---- prologue: stage first tile into buffer 0
    {
        int row = (blockIdx.x << 4) + sr;
        uint4 hv = make_uint4(0, 0, 0, 0), lv = make_uint4(0, 0, 0, 0);
        if (blockIdx.x < ntiles && row < Nn) {
            size_t gidx = (size_t)row * F + seg * 8;
            hv = *(const uint4*)&g_Shi[gidx];
            lv = *(const uint4*)&g_Slo[gidx];
        }
        *(uint4*)&Sa0[sr * SPAD + seg * 8] = hv;
        *(uint4*)&Sb0[sr * SPAD + seg * 8] = lv;
    }
    __syncthreads();

    int p = 0;
    for (int t = blockIdx.x; t < ntiles; t += gridDim.x) {
        int row0 = t << 4;

        // ---- prefetch next tile's S into regs (independent of mainloop)
        uint4 hvN = make_uint4(0, 0, 0, 0), lvN = make_uint4(0, 0, 0, 0);
        {
            int tn = t + gridDim.x;
            int row = (tn << 4) + sr;
            if (tn < ntiles && row < Nn) {
                size_t gidx = (size_t)row * F + seg * 8;
                hvN = *(const uint4*)&g_Shi[gidx];
                lvN = *(const uint4*)&g_Slo[gidx];
            }
        }

        // ---- prefetch current tile's x residuals (consumed at writeout)
        int r0 = row0 + m0;
        int r1 = r0 + 8;
        float2 xv[2][2];
        #pragma unroll
        for (int j = 0; j < 2; j++) {
            int col = (nt0 + j) * 8 + cq * 2;
            xv[j][0] = (r0 < Nn) ? *(const float2*)&x[(size_t)r0 * F + col]
                                 : make_float2(0.f, 0.f);
            xv[j][1] = (r1 < Nn) ? *(const float2*)&x[(size_t)r1 * F + col]
                                 : make_float2(0.f, 0.f);
        }

        // ---- mainloop from buffer p: 6 independent acc chains of depth 8
        u32 baseA = p ? aSa1 : aSa0;
        u32 baseB = p ? aSb1 : aSb0;

        float acc_hh[2][4] = {{0.f,0.f,0.f,0.f},{0.f,0.f,0.f,0.f}};
        float acc_lh[2][4] = {{0.f,0.f,0.f,0.f},{0.f,0.f,0.f,0.f}};
        float acc_hl[2][4] = {{0.f,0.f,0.f,0.f},{0.f,0.f,0.f,0.f}};

        #pragma unroll
        for (int ks = 0; ks < 8; ks++) {
            int kk = ks * 16 + kbase;
            u32 ah0, ah1, ah2, ah3, al0, al1, al2, al3;
            LDMATRIX_X4(ah0, ah1, ah2, ah3, baseA + ks * 32);
            LDMATRIX_X4(al0, al1, al2, al3, baseB + ks * 32);

            u32 b0l0 = *(const u32*)&wb0[kk];       // conflict-free LDS.32
            u32 b0l1 = *(const u32*)&wb0[kk + 8];
            u32 b1l0 = *(const u32*)&wb1[kk];
            u32 b1l1 = *(const u32*)&wb1[kk + 8];

            MMA_BF16(acc_hh[0], ah0, ah1, ah2, ah3, Bh[0][ks][0], Bh[0][ks][1]);
            MMA_BF16(acc_hh[1], ah0, ah1, ah2, ah3, Bh[1][ks][0], Bh[1][ks][1]);
            MMA_BF16(acc_lh[0], al0, al1, al2, al3, Bh[0][ks][0], Bh[0][ks][1]);
            MMA_BF16(acc_lh[1], al0, al1, al2, al3, Bh[1][ks][0], Bh[1][ks][1]);
            MMA_BF16(acc_hl[0], ah0, ah1, ah2, ah3, b0l0, b0l1);
            MMA_BF16(acc_hl[1], ah0, ah1, ah2, ah3, b1l0, b1l1);
        }

        // ---- stage next tile into buffer 1-p
        {
            u16* SaN = p ? Sa0 : Sa1;
            u16* SbN = p ? Sb0 : Sb1;
            *(uint4*)&SaN[sr * SPAD + seg * 8] = hvN;
            *(uint4*)&SbN[sr * SPAD + seg * 8] = lvN;
        }

        // ---- writeout: (hh + lh + hl) + prefetched x residual
        #pragma unroll
        for (int j = 0; j < 2; j++) {
            int col = (nt0 + j) * 8 + cq * 2;
            float d0 = acc_hh[j][0] + acc_lh[j][0] + acc_hl[j][0];
            float d1 = acc_hh[j][1] + acc_lh[j][1] + acc_hl[j][1];
            float d2 = acc_hh[j][2] + acc_lh[j][2] + acc_hl[j][2];
            float d3 = acc_hh[j][3] + acc_lh[j][3] + acc_hl[j][3];
            if (r0 < Nn) {
                float2 o = make_float2(d0 + xv[j][0].x, d1 + xv[j][0].y);
                *(float2*)&out[(size_t)r0 * F + col] = o;
            }
            if (r1 < Nn) {
                float2 o = make_float2(d2 + xv[j][1].x, d3 + xv[j][1].y);
                *(float2*)&out[(size_t)r1 * F + col] = o;
            }
        }

        __syncthreads();   // next-buffer writes visible; current buffer free
        p ^= 1;
    }
}

// ---------------------------------------------------------------------------
extern "C" void kernel_launch(void* const* d_in, const int* in_sizes, int n_in,
                              void* d_out, int out_size) {
    const float* x      = (const float*)d_in[0];
    const float* h0     = (const float*)d_in[1];
    const float* ew     = (const float*)d_in[2];
    const float* weight = (const float*)d_in[3];
    const float* lamda  = (const float*)d_in[4];
    const float* alpha  = (const float*)d_in[5];
    const int*   esrc   = (const int*)d_in[6];
    const int*   edst   = (const int*)d_in[7];
    const int*   lp     = (const int*)d_in[8];

    int Nn = in_sizes[0] / F;
    int E  = in_sizes[2];
    float* out = (float*)d_out;

    // 1) bucket fill (1 edge/thread)
    fill_kernel<<<(E + 255) / 256, 256>>>(ew, esrc, edst, E);

    // 2) gather + S fuse + bf16 split (one warp per row)
    long long gthreads = (long long)Nn * 32;
    gather_kernel<<<(int)((gthreads + 255) / 256), 256>>>(x, h0, alpha, Nn);

    // 3) HMMA epilogue, 6 independent MMA chains (+ counter reset)
    cudaFuncSetAttribute(mma_epilogue_kernel,
                         cudaFuncAttributeMaxDynamicSharedMemorySize, SMEM_EPI);
    mma_epilogue_kernel<<<296, 256, SMEM_EPI>>>(x, weight, lamda, lp, out, Nn);
}